// round 1
// baseline (speedup 1.0000x reference)
#include <cuda_runtime.h>
#include <cstdint>

// Problem constants (fixed by reference)
#define NB   8
#define HH   512
#define WW   512
#define DD   8
#define HWC  (HH * WW)          // 262144
#define NPIX (NB * HWC)         // 2097152
#define PPT  4                  // pixels per thread
#define NTHREADS (NPIX / PPT)   // 524288
#define TPB  256

// Flag: 1 if pix_to_face is int64, 0 if int32.
__device__ int g_is64;

// Detect element width of pix_to_face. If int64 (little-endian), the high
// 32-bit word of every element is 0 (value in [0, 8e5)) or 0xFFFFFFFF (-1).
// If int32, those word positions hold arbitrary face indices (~20% chance of
// matching 0/-1). 256-sample majority vote separates the cases decisively.
__global__ void detect_kernel(const unsigned int* __restrict__ p) {
    int lane = threadIdx.x;  // 32 lanes
    int cnt = 0;
    #pragma unroll
    for (int i = 0; i < 8; i++) {
        unsigned int hi = p[2 * (lane * 8 + i) + 1];
        cnt += (hi == 0u || hi == 0xFFFFFFFFu) ? 1 : 0;
    }
    #pragma unroll
    for (int s = 16; s; s >>= 1)
        cnt += __shfl_xor_sync(0xffffffffu, cnt, s);
    if (lane == 0)
        g_is64 = (cnt >= 200) ? 1 : 0;
}

__global__ __launch_bounds__(TPB, 2)
void interp_kernel(const void* __restrict__ p2f_raw,
                   const float* __restrict__ bary,
                   const float4* __restrict__ attr,   // [N*NF][3][8] fp32 = 6 float4 / face
                   float* __restrict__ out)           // [N][9][H][W]
{
    int t = blockIdx.x * blockDim.x + threadIdx.x;
    int pix0 = t * PPT;
    if (pix0 >= NPIX) return;

    // ---- face indices for 4 pixels (dtype-adaptive, uniform branch) ----
    long long f[PPT];
    if (g_is64) {
        const longlong2* p = (const longlong2*)p2f_raw + (pix0 >> 1);
        longlong2 v0 = p[0];
        longlong2 v1 = p[1];
        f[0] = v0.x; f[1] = v0.y; f[2] = v1.x; f[3] = v1.y;
    } else {
        int4 v = ((const int4*)p2f_raw)[pix0 >> 2];
        f[0] = v.x; f[1] = v.y; f[2] = v.z; f[3] = v.w;
    }

    // ---- barycentrics: 12 floats = 3 aligned float4 ----
    const float4* bp = (const float4*)(bary + (size_t)pix0 * 3);
    float4 bv0 = bp[0], bv1 = bp[1], bv2 = bp[2];
    float b[12] = { bv0.x, bv0.y, bv0.z, bv0.w,
                    bv1.x, bv1.y, bv1.z, bv1.w,
                    bv2.x, bv2.y, bv2.z, bv2.w };

    float o[PPT][DD];
    float vis[PPT];

    #pragma unroll
    for (int p = 0; p < PPT; p++) {
        float b0 = b[p * 3 + 0];
        float b1 = b[p * 3 + 1];
        float b2 = b[p * 3 + 2];
        if (f[p] < 0) {
            #pragma unroll
            for (int d = 0; d < DD; d++) o[p][d] = 0.0f;
            vis[p] = 0.0f;
        } else {
            const float4* a = attr + (size_t)f[p] * 6;
            float4 a0 = a[0], a1 = a[1];   // vertex 0, ch 0-3 / 4-7
            float4 a2 = a[2], a3 = a[3];   // vertex 1
            float4 a4 = a[4], a5 = a[5];   // vertex 2
            o[p][0] = b0 * a0.x + b1 * a2.x + b2 * a4.x;
            o[p][1] = b0 * a0.y + b1 * a2.y + b2 * a4.y;
            o[p][2] = b0 * a0.z + b1 * a2.z + b2 * a4.z;
            o[p][3] = b0 * a0.w + b1 * a2.w + b2 * a4.w;
            o[p][4] = b0 * a1.x + b1 * a3.x + b2 * a5.x;
            o[p][5] = b0 * a1.y + b1 * a3.y + b2 * a5.y;
            o[p][6] = b0 * a1.z + b1 * a3.z + b2 * a5.z;
            o[p][7] = b0 * a1.w + b1 * a3.w + b2 * a5.w;
            vis[p] = 1.0f;
        }
    }

    // ---- output: [N][9][H][W], 4 consecutive w-pixels -> STG.128 per plane ----
    int n  = pix0 / HWC;           // 4-pixel group never crosses n (HWC % 4 == 0)
    int hw = pix0 - n * HWC;
    float4* ob = (float4*)(out + (size_t)n * (DD + 1) * HWC + hw);
    const size_t plane4 = HWC / 4;
    #pragma unroll
    for (int d = 0; d < DD; d++)
        ob[(size_t)d * plane4] = make_float4(o[0][d], o[1][d], o[2][d], o[3][d]);
    ob[(size_t)DD * plane4] = make_float4(vis[0], vis[1], vis[2], vis[3]);
}

extern "C" void kernel_launch(void* const* d_in, const int* in_sizes, int n_in,
                              void* d_out, int out_size) {
    const void*   p2f  = d_in[0];                    // [N,H,W,1] int32 or int64
    const float*  bary = (const float*)d_in[1];      // [N,H,W,1,3] fp32
    const float4* attr = (const float4*)d_in[2];     // [N,NF,3,8] fp32
    float*        out  = (float*)d_out;              // [N,9,H,W] fp32

    detect_kernel<<<1, 32>>>((const unsigned int*)p2f);
    interp_kernel<<<NTHREADS / TPB, TPB>>>(p2f, bary, attr, out);
}